// round 1
// baseline (speedup 1.0000x reference)
#include <cuda_runtime.h>
#include <cuda_bf16.h>
#include <math.h>

// Problem constants (fixed shapes from reference)
#define BB   8
#define CC   512
#define NN_  2048
#define RR   (BB * NN_)      // 16384 positions
#define MLPH 2048
#define KH   9
#define PAD  4

// ---------------- scratch (device globals; no allocs allowed) ----------------
__device__ float g_Qln[(size_t)RR * CC];
__device__ float g_Kln[(size_t)RR * CC];
__device__ float g_Qt [(size_t)RR * CC];   // raw query, pos-major (residual)
__device__ float g_Kt [(size_t)RR * CC];   // raw key,   pos-major (for V proj)
__device__ float g_Qp [(size_t)RR * CC];
__device__ float g_Kp [(size_t)RR * CC];
__device__ float g_Vp [(size_t)RR * CC];
__device__ float g_X  [(size_t)RR * CC];   // query + attn, pos-major
__device__ float g_L2 [(size_t)RR * CC];   // LN2(x)
__device__ float g_H  [(size_t)RR * MLPH]; // gelu(x@w1+b1)
__device__ float g_H2 [(size_t)RR * CC];   // h @ w2 + b2

// ============================================================================
// K1: q = LN(query+query_embed), k = LN(key+key_embed)  (LN over channels)
// also transpose raw query/key to position-major.
// One block per position (b,n). Strided reads over C; coalesced writes.
// ============================================================================
__global__ __launch_bounds__(256) void k_ln_qk(
    const float* __restrict__ q,  const float* __restrict__ k,
    const float* __restrict__ qe, const float* __restrict__ ke,
    const float* __restrict__ gn, const float* __restrict__ bn)
{
    int r  = blockIdx.x;
    int bb = r >> 11;          // / NN_
    int n  = r & (NN_ - 1);
    int tid = threadIdx.x;
    size_t base = (size_t)bb * CC * NN_ + n;

    float qraw[2], kraw[2], qv[2], kv[2];
    float qs = 0.f, qss = 0.f, ks = 0.f, kss = 0.f;
#pragma unroll
    for (int i = 0; i < 2; i++) {
        int c = tid + i * 256;
        size_t idx = base + (size_t)c * NN_;
        qraw[i] = q[idx];
        kraw[i] = k[idx];
        qv[i] = qraw[i] + qe[idx];
        kv[i] = kraw[i] + ke[idx];
        qs += qv[i]; qss += qv[i] * qv[i];
        ks += kv[i]; kss += kv[i] * kv[i];
    }
    __shared__ float sm[4][8];
#pragma unroll
    for (int o = 16; o > 0; o >>= 1) {
        qs  += __shfl_down_sync(0xffffffffu, qs,  o);
        qss += __shfl_down_sync(0xffffffffu, qss, o);
        ks  += __shfl_down_sync(0xffffffffu, ks,  o);
        kss += __shfl_down_sync(0xffffffffu, kss, o);
    }
    if ((tid & 31) == 0) {
        int w = tid >> 5;
        sm[0][w] = qs; sm[1][w] = qss; sm[2][w] = ks; sm[3][w] = kss;
    }
    __syncthreads();
    float fqs = 0.f, fqss = 0.f, fks = 0.f, fkss = 0.f;
#pragma unroll
    for (int w = 0; w < 8; w++) {
        fqs += sm[0][w]; fqss += sm[1][w]; fks += sm[2][w]; fkss += sm[3][w];
    }
    const float invC = 1.0f / CC;
    float qm = fqs * invC, km = fks * invC;
    float qrs = rsqrtf(fqss * invC - qm * qm + 1e-5f);
    float krs = rsqrtf(fkss * invC - km * km + 1e-5f);

    size_t ob = (size_t)r * CC;
#pragma unroll
    for (int i = 0; i < 2; i++) {
        int c = tid + i * 256;
        float g = gn[c], bv = bn[c];
        g_Qln[ob + c] = (qv[i] - qm) * qrs * g + bv;
        g_Kln[ob + c] = (kv[i] - km) * krs * g + bv;
        g_Qt [ob + c] = qraw[i];
        g_Kt [ob + c] = kraw[i];
    }
}

// ============================================================================
// SGEMM: C[M,N] = A[M,K] * B(+bias), fp32, 128x128x16 tiles, 8x8/thread.
// BT=true : B is [N,K] row-major (weight [out,in], NT GEMM)
// BT=false: B is [K,N] row-major (NN GEMM)
// GELU: exact gelu epilogue
// ============================================================================
template <bool BT, bool GELU>
__global__ __launch_bounds__(256) void sgemm128(
    const float* __restrict__ A, const float* __restrict__ Bm,
    const float* __restrict__ bias, float* __restrict__ Cm,
    int M, int Nd, int K)
{
    __shared__ float As[16][128];
    __shared__ float Bs[16][132];

    int tid = threadIdx.x;
    int tx = tid & 15;         // 0..15 -> col group
    int ty = tid >> 4;         // 0..15 -> row group
    int brow = blockIdx.y * 128;
    int bcol = blockIdx.x * 128;

    float acc[8][8];
#pragma unroll
    for (int i = 0; i < 8; i++)
#pragma unroll
        for (int j = 0; j < 8; j++) acc[i][j] = 0.f;

    for (int k0 = 0; k0 < K; k0 += 16) {
        // load A tile (128 rows x 16 k), store transposed As[k][row]
#pragma unroll
        for (int i = 0; i < 2; i++) {
            int f   = tid + i * 256;       // 0..511
            int row = f >> 2;              // 0..127
            int c4  = (f & 3) * 4;         // 0,4,8,12
            float4 v = *(const float4*)&A[(size_t)(brow + row) * K + k0 + c4];
            As[c4 + 0][row] = v.x; As[c4 + 1][row] = v.y;
            As[c4 + 2][row] = v.z; As[c4 + 3][row] = v.w;
        }
        if (BT) {
#pragma unroll
            for (int i = 0; i < 2; i++) {
                int f   = tid + i * 256;
                int row = f >> 2;          // n index 0..127
                int c4  = (f & 3) * 4;
                float4 v = *(const float4*)&Bm[(size_t)(bcol + row) * K + k0 + c4];
                Bs[c4 + 0][row] = v.x; Bs[c4 + 1][row] = v.y;
                Bs[c4 + 2][row] = v.z; Bs[c4 + 3][row] = v.w;
            }
        } else {
#pragma unroll
            for (int i = 0; i < 2; i++) {
                int f   = tid + i * 256;
                int row = f >> 5;          // k index 0..15
                int c4  = (f & 31) * 4;    // n offset 0..124
                float4 v = *(const float4*)&Bm[(size_t)(k0 + row) * Nd + bcol + c4];
                *(float4*)&Bs[row][c4] = v;
            }
        }
        __syncthreads();
#pragma unroll
        for (int kk = 0; kk < 16; kk++) {
            float a[8], b[8];
            *(float4*)&a[0] = *(const float4*)&As[kk][ty * 8];
            *(float4*)&a[4] = *(const float4*)&As[kk][ty * 8 + 4];
            *(float4*)&b[0] = *(const float4*)&Bs[kk][tx * 8];
            *(float4*)&b[4] = *(const float4*)&Bs[kk][tx * 8 + 4];
#pragma unroll
            for (int i = 0; i < 8; i++)
#pragma unroll
                for (int j = 0; j < 8; j++)
                    acc[i][j] = fmaf(a[i], b[j], acc[i][j]);
        }
        __syncthreads();
    }

    // epilogue
    float bvals[8];
#pragma unroll
    for (int j = 0; j < 8; j++) bvals[j] = bias[bcol + tx * 8 + j];
#pragma unroll
    for (int i = 0; i < 8; i++) {
        int row = brow + ty * 8 + i;
        float out[8];
#pragma unroll
        for (int j = 0; j < 8; j++) {
            float v = acc[i][j] + bvals[j];
            if (GELU) v = 0.5f * v * (1.0f + erff(v * 0.70710678118654752f));
            out[j] = v;
        }
        *(float4*)&Cm[(size_t)row * Nd + bcol + tx * 8]     = *(float4*)&out[0];
        *(float4*)&Cm[(size_t)row * Nd + bcol + tx * 8 + 4] = *(float4*)&out[4];
    }
}

// ============================================================================
// K4: windowed attention + residual + LN2, one block per position.
// logits: w_j = <q_pos, k_{pos+j-4}>; padded j contributes logit 0 (zero-pad).
// weights = softmax(w) * C^-0.5 (softmax FIRST, then scale, per reference).
// attn_c = sum_j w_j * v_{pos+j-4,c};  x = query + attn;  L2 = LN2(x).
// ============================================================================
__global__ __launch_bounds__(256) void k_attn(
    const float* __restrict__ g2, const float* __restrict__ b2)
{
    int r  = blockIdx.x;
    int bb = r >> 11;
    int n  = r & (NN_ - 1);
    int tid = threadIdx.x;
    const float scale = 0.044194173824159216f;  // 512^-0.5

    bool   valid[KH];
    size_t nb[KH];
#pragma unroll
    for (int j = 0; j < KH; j++) {
        int nn = n + j - PAD;
        valid[j] = (nn >= 0) && (nn < NN_);
        nb[j] = valid[j] ? ((size_t)(bb * NN_ + nn)) * CC : 0;
    }

    size_t qb = (size_t)r * CC;
    float acc[KH];
#pragma unroll
    for (int j = 0; j < KH; j++) acc[j] = 0.f;

#pragma unroll
    for (int it = 0; it < 2; it++) {
        int c = tid + it * 256;
        float qv = g_Qp[qb + c];
#pragma unroll
        for (int j = 0; j < KH; j++)
            if (valid[j]) acc[j] = fmaf(qv, g_Kp[nb[j] + c], acc[j]);
    }

    __shared__ float sm[KH][8];
#pragma unroll
    for (int j = 0; j < KH; j++) {
#pragma unroll
        for (int o = 16; o > 0; o >>= 1)
            acc[j] += __shfl_down_sync(0xffffffffu, acc[j], o);
    }
    if ((tid & 31) == 0) {
        int w = tid >> 5;
#pragma unroll
        for (int j = 0; j < KH; j++) sm[j][w] = acc[j];
    }
    __syncthreads();
    __shared__ float wt[KH];
    if (tid < KH) {
        float s = 0.f;
#pragma unroll
        for (int w = 0; w < 8; w++) s += sm[tid][w];
        wt[tid] = s;
    }
    __syncthreads();

    // softmax over all 9 (invalid logits are exactly 0, matching zero-padding)
    float m = wt[0];
#pragma unroll
    for (int j = 1; j < KH; j++) m = fmaxf(m, wt[j]);
    float wj[KH], es = 0.f;
#pragma unroll
    for (int j = 0; j < KH; j++) { wj[j] = expf(wt[j] - m); es += wj[j]; }
    float inv = scale / es;
#pragma unroll
    for (int j = 0; j < KH; j++) wj[j] *= inv;

    // weighted aggregation + residual, then LN2 stats
    float xv[2], xs = 0.f, xss = 0.f;
#pragma unroll
    for (int it = 0; it < 2; it++) {
        int c = tid + it * 256;
        float s = 0.f;
#pragma unroll
        for (int j = 0; j < KH; j++)
            if (valid[j]) s = fmaf(wj[j], g_Vp[nb[j] + c], s);
        float x = g_Qt[qb + c] + s;
        g_X[qb + c] = x;
        xv[it] = x; xs += x; xss += x * x;
    }
    __syncthreads();   // sm reuse
#pragma unroll
    for (int o = 16; o > 0; o >>= 1) {
        xs  += __shfl_down_sync(0xffffffffu, xs,  o);
        xss += __shfl_down_sync(0xffffffffu, xss, o);
    }
    if ((tid & 31) == 0) { int w = tid >> 5; sm[0][w] = xs; sm[1][w] = xss; }
    __syncthreads();
    float fs = 0.f, fss = 0.f;
#pragma unroll
    for (int w = 0; w < 8; w++) { fs += sm[0][w]; fss += sm[1][w]; }
    const float invC = 1.0f / CC;
    float mean = fs * invC;
    float rstd = rsqrtf(fss * invC - mean * mean + 1e-5f);
#pragma unroll
    for (int it = 0; it < 2; it++) {
        int c = tid + it * 256;
        g_L2[qb + c] = (xv[it] - mean) * rstd * g2[c] + b2[c];
    }
}

// ============================================================================
// K7: out[b,c,n] = X[r,c] + H2[r,c]   (pos-major -> channel-major transpose)
// ============================================================================
__global__ __launch_bounds__(256) void k_out(float* __restrict__ out)
{
    __shared__ float t[32][33];
    int bb = blockIdx.z;
    int c0 = blockIdx.y * 32;
    int n0 = blockIdx.x * 32;
    int tx = threadIdx.x;      // 0..31
    int ty = threadIdx.y;      // 0..7
#pragma unroll
    for (int i = 0; i < 4; i++) {
        int n = n0 + ty + i * 8;
        size_t idx = ((size_t)(bb * NN_ + n)) * CC + c0 + tx;
        t[tx][ty + i * 8] = g_X[idx] + g_H2[idx];
    }
    __syncthreads();
#pragma unroll
    for (int i = 0; i < 4; i++) {
        int c = c0 + ty + i * 8;
        out[(size_t)bb * CC * NN_ + (size_t)c * NN_ + n0 + tx] = t[ty + i * 8][tx];
    }
}

// ============================================================================
extern "C" void kernel_launch(void* const* d_in, const int* in_sizes, int n_in,
                              void* d_out, int out_size)
{
    const float* query = (const float*)d_in[0];
    const float* key   = (const float*)d_in[1];
    const float* qe    = (const float*)d_in[2];
    const float* ke    = (const float*)d_in[3];
    const float* wq    = (const float*)d_in[4];
    const float* bq    = (const float*)d_in[5];
    const float* wk    = (const float*)d_in[6];
    const float* bk    = (const float*)d_in[7];
    const float* wv    = (const float*)d_in[8];
    const float* bv    = (const float*)d_in[9];
    const float* gn    = (const float*)d_in[10];
    const float* bn    = (const float*)d_in[11];
    const float* g2    = (const float*)d_in[12];
    const float* b2    = (const float*)d_in[13];
    const float* w1    = (const float*)d_in[14];
    const float* b1    = (const float*)d_in[15];
    const float* w2    = (const float*)d_in[16];
    const float* b2b   = (const float*)d_in[17];
    float* out = (float*)d_out;

    float *Qln, *Kln, *Kt, *Qp, *Kp, *Vp, *L2, *H, *H2;
    cudaGetSymbolAddress((void**)&Qln, g_Qln);
    cudaGetSymbolAddress((void**)&Kln, g_Kln);
    cudaGetSymbolAddress((void**)&Kt,  g_Kt);
    cudaGetSymbolAddress((void**)&Qp,  g_Qp);
    cudaGetSymbolAddress((void**)&Kp,  g_Kp);
    cudaGetSymbolAddress((void**)&Vp,  g_Vp);
    cudaGetSymbolAddress((void**)&L2,  g_L2);
    cudaGetSymbolAddress((void**)&H,   g_H);
    cudaGetSymbolAddress((void**)&H2,  g_H2);

    // 1) add + LN + transpose
    k_ln_qk<<<RR, 256>>>(query, key, qe, ke, gn, bn);

    // 2) projections: NT GEMMs  [16384,512] x [512,512]^T
    {
        dim3 g(CC / 128, RR / 128);
        sgemm128<true, false><<<g, 256>>>(Qln, wq, bq, Qp, RR, CC, CC);
        sgemm128<true, false><<<g, 256>>>(Kln, wk, bk, Kp, RR, CC, CC);
        sgemm128<true, false><<<g, 256>>>(Kt,  wv, bv, Vp, RR, CC, CC);
    }

    // 3) windowed attention + residual + LN2
    k_attn<<<RR, 256>>>(g2, b2);

    // 4) MLP: H = gelu(L2 @ w1 + b1)   [16384,512]x[512,2048]
    {
        dim3 g(MLPH / 128, RR / 128);
        sgemm128<false, true><<<g, 256>>>(L2, w1, b1, H, RR, MLPH, CC);
    }
    // 5) H2 = H @ w2 + b2b             [16384,2048]x[2048,512]
    {
        dim3 g(CC / 128, RR / 128);
        sgemm128<false, false><<<g, 256>>>(H, w2, b2b, H2, RR, CC, MLPH);
    }

    // 6) out = transpose(X + H2)
    {
        dim3 g(NN_ / 32, CC / 32, BB);
        dim3 blk(32, 8);
        k_out<<<g, blk>>>(out);
    }
}

// round 6
// speedup vs baseline: 2.2109x; 2.2109x over previous
#include <cuda_runtime.h>
#include <cuda_bf16.h>
#include <math.h>
#include <stdint.h>

// Problem constants (fixed shapes)
#define BB   8
#define CC   512
#define NN_  2048
#define RR   (BB * NN_)      // 16384 positions
#define MLPH 2048
#define KH   9
#define PAD  4

// ---------------- scratch (device globals; no allocs allowed) ----------------
__device__ __align__(16) float g_Qt [(size_t)RR * CC];   // raw query (residual)
__device__ __align__(16) float g_Qp [(size_t)RR * CC];
__device__ __align__(16) float g_Kp [(size_t)RR * CC];
__device__ __align__(16) float g_Vp [(size_t)RR * CC];
__device__ __align__(16) float g_X  [(size_t)RR * CC];
__device__ __align__(16) float g_H2 [(size_t)RR * CC];

__device__ __align__(16) __nv_bfloat16 g_Qh[(size_t)RR * CC],  g_Ql[(size_t)RR * CC];
__device__ __align__(16) __nv_bfloat16 g_Kh[(size_t)RR * CC],  g_Kl[(size_t)RR * CC];
__device__ __align__(16) __nv_bfloat16 g_Vh[(size_t)RR * CC],  g_Vl[(size_t)RR * CC];
__device__ __align__(16) __nv_bfloat16 g_L2h[(size_t)RR * CC], g_L2l[(size_t)RR * CC];
__device__ __align__(16) __nv_bfloat16 g_Hh[(size_t)RR * MLPH], g_Hl[(size_t)RR * MLPH];

__device__ __align__(16) __nv_bfloat16 g_wqh[CC * CC],  g_wql[CC * CC];
__device__ __align__(16) __nv_bfloat16 g_wkh[CC * CC],  g_wkl[CC * CC];
__device__ __align__(16) __nv_bfloat16 g_wvh[CC * CC],  g_wvl[CC * CC];
__device__ __align__(16) __nv_bfloat16 g_w1h[MLPH * CC], g_w1l[MLPH * CC]; // w1^T
__device__ __align__(16) __nv_bfloat16 g_w2h[CC * MLPH], g_w2l[CC * MLPH]; // w2^T

// ---------------- helpers ----------------------------------------------------
__device__ __forceinline__ uint32_t smem_u32(const void* p) {
    uint32_t a;
    asm("{ .reg .u64 t; cvta.to.shared.u64 t, %1; cvt.u32.u64 %0, t; }"
        : "=r"(a) : "l"(p));
    return a;
}
__device__ __forceinline__ void cpa16(uint32_t dst, const void* src) {
    asm volatile("cp.async.cg.shared.global [%0], [%1], 16;"
                 :: "r"(dst), "l"(src) : "memory");
}
#define CP_COMMIT() asm volatile("cp.async.commit_group;" ::: "memory")
#define CP_WAIT(n)  asm volatile("cp.async.wait_group %0;" :: "n"(n) : "memory")

__device__ __forceinline__ void ldsm4(uint32_t& r0, uint32_t& r1,
                                      uint32_t& r2, uint32_t& r3, uint32_t a) {
    asm volatile("ldmatrix.sync.aligned.m8n8.x4.shared.b16 {%0,%1,%2,%3}, [%4];"
                 : "=r"(r0), "=r"(r1), "=r"(r2), "=r"(r3) : "r"(a));
}
__device__ __forceinline__ void mma16816(float* c, uint32_t a0, uint32_t a1,
                                         uint32_t a2, uint32_t a3,
                                         uint32_t b0, uint32_t b1) {
    asm volatile(
        "mma.sync.aligned.m16n8k16.row.col.f32.bf16.bf16.f32 "
        "{%0,%1,%2,%3}, {%4,%5,%6,%7}, {%8,%9}, {%0,%1,%2,%3};"
        : "+f"(c[0]), "+f"(c[1]), "+f"(c[2]), "+f"(c[3])
        : "r"(a0), "r"(a1), "r"(a2), "r"(a3), "r"(b0), "r"(b1));
}
__device__ __forceinline__ void bf16_split(float v, __nv_bfloat16& h, __nv_bfloat16& l) {
    h = __float2bfloat16(v);
    l = __float2bfloat16(v - __bfloat162float(h));
}
// smem layout: rows of 32 bf16 (64B); 16B units XOR-swizzled by (row>>1)&3
__device__ __forceinline__ uint32_t swoff(int row, int kb) {
    return (uint32_t)((row << 6) + ((((kb >> 4) ^ ((row >> 1) & 3))) << 4));
}

// ============================================================================
// K1: LN(q+qe), LN(k+ke) -> bf16 hi/lo; raw key -> bf16 hi/lo; raw query fp32.
// ============================================================================
__global__ __launch_bounds__(256) void k_ln_qk(
    const float* __restrict__ q,  const float* __restrict__ k,
    const float* __restrict__ qe, const float* __restrict__ ke,
    const float* __restrict__ gn, const float* __restrict__ bn)
{
    int r  = blockIdx.x;
    int bb = r >> 11;
    int n  = r & (NN_ - 1);
    int tid = threadIdx.x;
    size_t base = (size_t)bb * CC * NN_ + n;

    float qraw[2], kraw[2], qv[2], kv[2];
    float qs = 0.f, qss = 0.f, ks = 0.f, kss = 0.f;
#pragma unroll
    for (int i = 0; i < 2; i++) {
        int c = tid + i * 256;
        size_t idx = base + (size_t)c * NN_;
        qraw[i] = q[idx];
        kraw[i] = k[idx];
        qv[i] = qraw[i] + qe[idx];
        kv[i] = kraw[i] + ke[idx];
        qs += qv[i]; qss += qv[i] * qv[i];
        ks += kv[i]; kss += kv[i] * kv[i];
    }
    __shared__ float sm[4][8];
#pragma unroll
    for (int o = 16; o > 0; o >>= 1) {
        qs  += __shfl_down_sync(0xffffffffu, qs,  o);
        qss += __shfl_down_sync(0xffffffffu, qss, o);
        ks  += __shfl_down_sync(0xffffffffu, ks,  o);
        kss += __shfl_down_sync(0xffffffffu, kss, o);
    }
    if ((tid & 31) == 0) {
        int w = tid >> 5;
        sm[0][w] = qs; sm[1][w] = qss; sm[2][w] = ks; sm[3][w] = kss;
    }
    __syncthreads();
    float fqs = 0.f, fqss = 0.f, fks = 0.f, fkss = 0.f;
#pragma unroll
    for (int w = 0; w < 8; w++) {
        fqs += sm[0][w]; fqss += sm[1][w]; fks += sm[2][w]; fkss += sm[3][w];
    }
    const float invC = 1.0f / CC;
    float qm = fqs * invC, km = fks * invC;
    float qrs = rsqrtf(fqss * invC - qm * qm + 1e-5f);
    float krs = rsqrtf(fkss * invC - km * km + 1e-5f);

    size_t ob = (size_t)r * CC;
#pragma unroll
    for (int i = 0; i < 2; i++) {
        int c = tid + i * 256;
        float g = gn[c], bv = bn[c];
        float qo = (qv[i] - qm) * qrs * g + bv;
        float ko = (kv[i] - km) * krs * g + bv;
        __nv_bfloat16 h, l;
        bf16_split(qo, h, l);      g_Qh[ob + c] = h; g_Ql[ob + c] = l;
        bf16_split(ko, h, l);      g_Kh[ob + c] = h; g_Kl[ob + c] = l;
        bf16_split(kraw[i], h, l); g_Vh[ob + c] = h; g_Vl[ob + c] = l;
        g_Qt[ob + c] = qraw[i];
    }
}

// ============================================================================
// mma.sync split-bf16 GEMM:  C[M,Nd] = A[M,K] * B[Nd,K]^T (+bias)
// 128x128x32 CTA tile, 8 warps (2x4), warp tile 64x32, double-buffered cp.async.
// OUT=0: fp32 store.  OUT=1: exact-GELU then bf16 hi/lo split store.
// ============================================================================
#define ST_BYTES 32768          // per stage: Ah 8K | Al 8K | Bh 8K | Bl 8K
#define GEMM_SMEM (2 * ST_BYTES)

__device__ __forceinline__ void ld_tile(uint32_t sdst,
                                        const __nv_bfloat16* __restrict__ src,
                                        int ldk) {
    int tid = threadIdx.x;
#pragma unroll
    for (int it = 0; it < 2; it++) {
        int f   = tid + it * 256;   // 0..511
        int row = f >> 2;           // 0..127
        int u   = f & 3;            // 16B unit within 64B row
        uint32_t d = sdst + (uint32_t)(row << 6) + (uint32_t)(((u ^ ((row >> 1) & 3))) << 4);
        cpa16(d, src + (size_t)row * ldk + u * 8);
    }
}

template <int OUT>
__global__ __launch_bounds__(256, 1) void mma_gemm(
    const __nv_bfloat16* __restrict__ Ahi, const __nv_bfloat16* __restrict__ Alo,
    const __nv_bfloat16* __restrict__ Bhi, const __nv_bfloat16* __restrict__ Blo,
    const float* __restrict__ bias,
    float* __restrict__ Cf,
    __nv_bfloat16* __restrict__ Chi, __nv_bfloat16* __restrict__ Clo,
    int M, int Nd, int K)
{
    extern __shared__ char smem[];
    uint32_t sb = smem_u32(smem);
    const int tid  = threadIdx.x;
    const int lane = tid & 31;
    const int wid  = tid >> 5;
    const int wr   = wid >> 2;          // 0..1 (64 m rows)
    const int wc   = wid & 3;           // 0..3 (32 n cols)
    const int brow = blockIdx.y * 128;
    const int bcol = blockIdx.x * 128;

    float acc[4][4][4];
#pragma unroll
    for (int i = 0; i < 4; i++)
#pragma unroll
        for (int j = 0; j < 4; j++)
#pragma unroll
            for (int x = 0; x < 4; x++) acc[i][j][x] = 0.f;

    // lane-invariant ldmatrix geometry
    const int a_row = wr * 64 + (lane & 15);
    const int a_kb  = (lane & 16);              // 0 or 16 bytes
    const int b_row = wc * 32 + (lane & 7) + ((lane & 16) ? 8 : 0);
    const int b_kb  = ((lane & 8) ? 16 : 0);

    const int NCH = K >> 5;   // 32-k chunks

    // prologue
    {
        uint32_t s0 = sb;
        ld_tile(s0 +     0, Ahi + (size_t)brow * K, K);
        ld_tile(s0 +  8192, Alo + (size_t)brow * K, K);
        ld_tile(s0 + 16384, Bhi + (size_t)bcol * K, K);
        ld_tile(s0 + 24576, Blo + (size_t)bcol * K, K);
        CP_COMMIT();
    }

    for (int ch = 0; ch < NCH; ch++) {
        int s = ch & 1;
        if (ch + 1 < NCH) {
            uint32_t sn = sb + (uint32_t)((s ^ 1) * ST_BYTES);
            int k0 = (ch + 1) << 5;
            ld_tile(sn +     0, Ahi + (size_t)brow * K + k0, K);
            ld_tile(sn +  8192, Alo + (size_t)brow * K + k0, K);
            ld_tile(sn + 16384, Bhi + (size_t)bcol * K + k0, K);
            ld_tile(sn + 24576, Blo + (size_t)bcol * K + k0, K);
            CP_COMMIT();
            CP_WAIT(1);
        } else {
            CP_WAIT(0);
        }
        __syncthreads();

        uint32_t sa = sb + (uint32_t)(s * ST_BYTES);
#pragma unroll
        for (int ks = 0; ks < 2; ks++) {
            int kso = ks * 32;
            uint32_t bh[4][2], bl[4][2];
#pragma unroll
            for (int jp = 0; jp < 2; jp++) {
                uint32_t addr_h = sa + 16384 + swoff(b_row + jp * 16, b_kb + kso);
                uint32_t addr_l = sa + 24576 + swoff(b_row + jp * 16, b_kb + kso);
                ldsm4(bh[2*jp][0], bh[2*jp][1], bh[2*jp+1][0], bh[2*jp+1][1], addr_h);
                ldsm4(bl[2*jp][0], bl[2*jp][1], bl[2*jp+1][0], bl[2*jp+1][1], addr_l);
            }
#pragma unroll
            for (int i = 0; i < 4; i++) {
                uint32_t ah0, ah1, ah2, ah3, al0, al1, al2, al3;
                ldsm4(ah0, ah1, ah2, ah3, sa +    0 + swoff(a_row + i * 16, a_kb + kso));
                ldsm4(al0, al1, al2, al3, sa + 8192 + swoff(a_row + i * 16, a_kb + kso));
#pragma unroll
                for (int j = 0; j < 4; j++) {
                    mma16816(acc[i][j], ah0, ah1, ah2, ah3, bh[j][0], bh[j][1]);
                    mma16816(acc[i][j], ah0, ah1, ah2, ah3, bl[j][0], bl[j][1]);
                    mma16816(acc[i][j], al0, al1, al2, al3, bh[j][0], bh[j][1]);
                }
            }
        }
        __syncthreads();
    }

    // epilogue
    const int grp = lane >> 2, qr = lane & 3;
#pragma unroll
    for (int i = 0; i < 4; i++) {
        int r0 = brow + wr * 64 + i * 16 + grp;
#pragma unroll
        for (int j = 0; j < 4; j++) {
            int col = bcol + wc * 32 + j * 8 + qr * 2;
            float b0 = bias[col], b1 = bias[col + 1];
            float v00 = acc[i][j][0] + b0, v01 = acc[i][j][1] + b1;
            float v10 = acc[i][j][2] + b0, v11 = acc[i][j][3] + b1;
            if (OUT == 0) {
                *(float2*)(Cf + (size_t)r0 * Nd + col)       = make_float2(v00, v01);
                *(float2*)(Cf + (size_t)(r0 + 8) * Nd + col) = make_float2(v10, v11);
            } else {
                v00 = 0.5f * v00 * (1.0f + erff(v00 * 0.70710678118654752f));
                v01 = 0.5f * v01 * (1.0f + erff(v01 * 0.70710678118654752f));
                v10 = 0.5f * v10 * (1.0f + erff(v10 * 0.70710678118654752f));
                v11 = 0.5f * v11 * (1.0f + erff(v11 * 0.70710678118654752f));
                __nv_bfloat16 h0, l0, h1, l1;
                bf16_split(v00, h0, l0); bf16_split(v01, h1, l1);
                *(__nv_bfloat162*)(Chi + (size_t)r0 * Nd + col) = __nv_bfloat162(h0, h1);
                *(__nv_bfloat162*)(Clo + (size_t)r0 * Nd + col) = __nv_bfloat162(l0, l1);
                bf16_split(v10, h0, l0); bf16_split(v11, h1, l1);
                *(__nv_bfloat162*)(Chi + (size_t)(r0 + 8) * Nd + col) = __nv_bfloat162(h0, h1);
                *(__nv_bfloat162*)(Clo + (size_t)(r0 + 8) * Nd + col) = __nv_bfloat162(l0, l1);
            }
        }
    }
}

// ============================================================================
// K4: windowed attention + residual + LN2 (emits bf16 hi/lo for MLP).
// ============================================================================
__global__ __launch_bounds__(256) void k_attn(
    const float* __restrict__ g2, const float* __restrict__ b2)
{
    int r  = blockIdx.x;
    int bb = r >> 11;
    int n  = r & (NN_ - 1);
    int tid = threadIdx.x;
    const float scale = 0.044194173824159216f;  // 512^-0.5

    bool   valid[KH];
    size_t nb[KH];
#pragma unroll
    for (int j = 0; j < KH; j++) {
        int nn = n + j - PAD;
        valid[j] = (nn >= 0) && (nn < NN_);
        nb[j] = valid[j] ? ((size_t)(bb * NN_ + nn)) * CC : 0;
    }

    size_t qb = (size_t)r * CC;
    float acc[KH];
#pragma unroll
    for (int j = 0; j < KH; j++) acc[j] = 0.f;

#pragma unroll
    for (int it = 0; it < 2; it++) {
        int c = tid + it * 256;
        float qv = g_Qp[qb + c];
#pragma unroll
        for (int j = 0; j < KH; j++)
            if (valid[j]) acc[j] = fmaf(qv, g_Kp[nb[j] + c], acc[j]);
    }

    __shared__ float sm[KH][8];
#pragma unroll
    for (int j = 0; j < KH; j++) {
#pragma unroll
        for (int o = 16; o > 0; o >>= 1)
            acc[j] += __shfl_down_sync(0xffffffffu, acc[j], o);
    }
    if ((tid & 31) == 0) {
        int w = tid >> 5;
#pragma unroll
        for (int j = 0; j < KH; j++) sm[j][w] = acc[j];
    }
    __syncthreads();
    __shared__ float wt[KH];
    if (tid < KH) {
        float s = 0.f;
#pragma unroll
        for (int w = 0; w < 8; w++) s += sm[tid][w];
        wt[tid] = s;
    }
    __syncthreads();

    float m = wt[0];
#pragma unroll
    for (int j = 1; j < KH; j++) m = fmaxf(m, wt[j]);
    float wj[KH], es = 0.f;
#pragma unroll
    for (int j = 0; j < KH; j++) { wj[j] = expf(wt[j] - m); es += wj[j]; }
    float inv = scale / es;
#pragma unroll
    for (int j = 0; j < KH; j++) wj[j] *= inv;

    float xv[2], xs = 0.f, xss = 0.f;
#pragma unroll
    for (int it = 0; it < 2; it++) {
        int c = tid + it * 256;
        float s = 0.f;
#pragma unroll
        for (int j = 0; j < KH; j++)
            if (valid[j]) s = fmaf(wj[j], g_Vp[nb[j] + c], s);
        float x = g_Qt[qb + c] + s;
        g_X[qb + c] = x;
        xv[it] = x; xs += x; xss += x * x;
    }
    __syncthreads();
#pragma unroll
    for (int o = 16; o > 0; o >>= 1) {
        xs  += __shfl_down_sync(0xffffffffu, xs,  o);
        xss += __shfl_down_sync(0xffffffffu, xss, o);
    }
    if ((tid & 31) == 0) { int w = tid >> 5; sm[0][w] = xs; sm[1][w] = xss; }
    __syncthreads();
    float fs = 0.f, fss = 0.f;
#pragma unroll
    for (int w = 0; w < 8; w++) { fs += sm[0][w]; fss += sm[1][w]; }
    const float invC = 1.0f / CC;
    float mean = fs * invC;
    float rstd = rsqrtf(fss * invC - mean * mean + 1e-5f);
#pragma unroll
    for (int it = 0; it < 2; it++) {
        int c = tid + it * 256;
        float v = (xv[it] - mean) * rstd * g2[c] + b2[c];
        __nv_bfloat16 h, l;
        bf16_split(v, h, l);
        g_L2h[qb + c] = h; g_L2l[qb + c] = l;
    }
}

// ============================================================================
// weight prep
// ============================================================================
__global__ __launch_bounds__(256) void k_cvt(
    const float* __restrict__ src, __nv_bfloat16* __restrict__ hi,
    __nv_bfloat16* __restrict__ lo, int n)
{
    int i = blockIdx.x * 256 + threadIdx.x;
    if (i < n) {
        __nv_bfloat16 h, l;
        bf16_split(src[i], h, l);
        hi[i] = h; lo[i] = l;
    }
}

// src [R, Cc] fp32 -> dst [Cc, R] bf16 hi/lo
__global__ void k_tcvt(const float* __restrict__ src,
                       __nv_bfloat16* __restrict__ hi,
                       __nv_bfloat16* __restrict__ lo, int R, int Cc)
{
    __shared__ float t[32][33];
    int c0 = blockIdx.x * 32, r0 = blockIdx.y * 32;
    int tx = threadIdx.x, ty = threadIdx.y;
#pragma unroll
    for (int i = 0; i < 4; i++)
        t[ty + i * 8][tx] = src[(size_t)(r0 + ty + i * 8) * Cc + c0 + tx];
    __syncthreads();
#pragma unroll
    for (int i = 0; i < 4; i++) {
        float v = t[tx][ty + i * 8];
        size_t o = (size_t)(c0 + ty + i * 8) * R + r0 + tx;
        __nv_bfloat16 h, l;
        bf16_split(v, h, l);
        hi[o] = h; lo[o] = l;
    }
}

// ============================================================================
// K7: out[b,c,n] = X[r,c] + H2[r,c]
// ============================================================================
__global__ __launch_bounds__(256) void k_out(float* __restrict__ out)
{
    __shared__ float t[32][33];
    int bb = blockIdx.z;
    int c0 = blockIdx.y * 32;
    int n0 = blockIdx.x * 32;
    int tx = threadIdx.x;
    int ty = threadIdx.y;
#pragma unroll
    for (int i = 0; i < 4; i++) {
        int n = n0 + ty + i * 8;
        size_t idx = ((size_t)(bb * NN_ + n)) * CC + c0 + tx;
        t[tx][ty + i * 8] = g_X[idx] + g_H2[idx];
    }
    __syncthreads();
#pragma unroll
    for (int i = 0; i < 4; i++) {
        int c = c0 + ty + i * 8;
        out[(size_t)bb * CC * NN_ + (size_t)c * NN_ + n0 + tx] = t[ty + i * 8][tx];
    }
}

// ============================================================================
extern "C" void kernel_launch(void* const* d_in, const int* in_sizes, int n_in,
                              void* d_out, int out_size)
{
    const float* query = (const float*)d_in[0];
    const float* key   = (const float*)d_in[1];
    const float* qe    = (const float*)d_in[2];
    const float* ke    = (const float*)d_in[3];
    const float* wq    = (const float*)d_in[4];
    const float* bq    = (const float*)d_in[5];
    const float* wk    = (const float*)d_in[6];
    const float* bk    = (const float*)d_in[7];
    const float* wv    = (const float*)d_in[8];
    const float* bv    = (const float*)d_in[9];
    const float* gn    = (const float*)d_in[10];
    const float* bn    = (const float*)d_in[11];
    const float* g2    = (const float*)d_in[12];
    const float* b2    = (const float*)d_in[13];
    const float* w1    = (const float*)d_in[14];
    const float* b1    = (const float*)d_in[15];
    const float* w2    = (const float*)d_in[16];
    const float* b2b   = (const float*)d_in[17];
    float* out = (float*)d_out;

    float *Qp, *Kp, *Vp, *H2;
    __nv_bfloat16 *Qh, *Ql, *Kh, *Kl, *Vh, *Vl, *L2h, *L2l, *Hh, *Hl;
    __nv_bfloat16 *wqh, *wql, *wkh, *wkl, *wvh, *wvl, *w1h, *w1l, *w2h, *w2l;
    cudaGetSymbolAddress((void**)&Qp,  g_Qp);
    cudaGetSymbolAddress((void**)&Kp,  g_Kp);
    cudaGetSymbolAddress((void**)&Vp,  g_Vp);
    cudaGetSymbolAddress((void**)&H2,  g_H2);
    cudaGetSymbolAddress((void**)&Qh,  g_Qh);  cudaGetSymbolAddress((void**)&Ql,  g_Ql);
    cudaGetSymbolAddress((void**)&Kh,  g_Kh);  cudaGetSymbolAddress((void**)&Kl,  g_Kl);
    cudaGetSymbolAddress((void**)&Vh,  g_Vh);  cudaGetSymbolAddress((void**)&Vl,  g_Vl);
    cudaGetSymbolAddress((void**)&L2h, g_L2h); cudaGetSymbolAddress((void**)&L2l, g_L2l);
    cudaGetSymbolAddress((void**)&Hh,  g_Hh);  cudaGetSymbolAddress((void**)&Hl,  g_Hl);
    cudaGetSymbolAddress((void**)&wqh, g_wqh); cudaGetSymbolAddress((void**)&wql, g_wql);
    cudaGetSymbolAddress((void**)&wkh, g_wkh); cudaGetSymbolAddress((void**)&wkl, g_wkl);
    cudaGetSymbolAddress((void**)&wvh, g_wvh); cudaGetSymbolAddress((void**)&wvl, g_wvl);
    cudaGetSymbolAddress((void**)&w1h, g_w1h); cudaGetSymbolAddress((void**)&w1l, g_w1l);
    cudaGetSymbolAddress((void**)&w2h, g_w2h); cudaGetSymbolAddress((void**)&w2l, g_w2l);

    cudaFuncSetAttribute(mma_gemm<0>, cudaFuncAttributeMaxDynamicSharedMemorySize, GEMM_SMEM);
    cudaFuncSetAttribute(mma_gemm<1>, cudaFuncAttributeMaxDynamicSharedMemorySize, GEMM_SMEM);

    // weight prep
    k_cvt<<<(CC * CC + 255) / 256, 256>>>(wq, wqh, wql, CC * CC);
    k_cvt<<<(CC * CC + 255) / 256, 256>>>(wk, wkh, wkl, CC * CC);
    k_cvt<<<(CC * CC + 255) / 256, 256>>>(wv, wvh, wvl, CC * CC);
    k_tcvt<<<dim3(MLPH / 32, CC / 32), dim3(32, 8)>>>(w1, w1h, w1l, CC, MLPH);
    k_tcvt<<<dim3(CC / 32, MLPH / 32), dim3(32, 8)>>>(w2, w2h, w2l, MLPH, CC);

    // 1) add + LN (+ bf16 splits)
    k_ln_qk<<<RR, 256>>>(query, key, qe, ke, gn, bn);

    // 2) projections (NT, K=512): [16384,512] x [512,512]^T
    {
        dim3 g(CC / 128, RR / 128);
        mma_gemm<0><<<g, 256, GEMM_SMEM>>>(Qh, Ql, wqh, wql, bq, Qp, nullptr, nullptr, RR, CC, CC);
        mma_gemm<0><<<g, 256, GEMM_SMEM>>>(Kh, Kl, wkh, wkl, bk, Kp, nullptr, nullptr, RR, CC, CC);
        mma_gemm<0><<<g, 256, GEMM_SMEM>>>(Vh, Vl, wvh, wvl, bv, Vp, nullptr, nullptr, RR, CC, CC);
    }

    // 3) attention + residual + LN2
    k_attn<<<RR, 256>>>(g2, b2);

    // 4) MLP1: H = gelu(L2 @ w1^T + b1)   Nd=2048, K=512
    {
        dim3 g(MLPH / 128, RR / 128);
        mma_gemm<1><<<g, 256, GEMM_SMEM>>>(L2h, L2l, w1h, w1l, b1, nullptr, Hh, Hl, RR, MLPH, CC);
    }
    // 5) H2 = H @ w2^T + b2b              Nd=512, K=2048
    {
        dim3 g(CC / 128, RR / 128);
        mma_gemm<0><<<g, 256, GEMM_SMEM>>>(Hh, Hl, w2h, w2l, b2b, H2, nullptr, nullptr, RR, CC, MLPH);
    }

    // 6) out = transpose(X + H2)
    {
        dim3 g(NN_ / 32, CC / 32, BB);
        dim3 blk(32, 8);
        k_out<<<g, blk>>>(out);
    }
}

// round 7
// speedup vs baseline: 2.7728x; 1.2542x over previous
#include <cuda_runtime.h>
#include <cuda_bf16.h>
#include <math.h>
#include <stdint.h>

// Problem constants (fixed shapes)
#define BB   8
#define CC   512
#define NN_  2048
#define RR   (BB * NN_)      // 16384 positions
#define MLPH 2048
#define KH   9
#define PAD  4

// ---------------- scratch (device globals; no allocs allowed) ----------------
__device__ __align__(16) float g_Qt [(size_t)RR * CC];   // raw query (residual)
__device__ __align__(16) float g_Qp [(size_t)RR * CC];
__device__ __align__(16) float g_Kp [(size_t)RR * CC];
__device__ __align__(16) float g_Vp [(size_t)RR * CC];
__device__ __align__(16) float g_X  [(size_t)RR * CC];
__device__ __align__(16) float g_H2 [(size_t)RR * CC];
__device__ __align__(16) float4 g_stats[RR];             // qm,qrs,km,krs

__device__ __align__(16) __nv_bfloat16 g_Qh[(size_t)RR * CC],  g_Ql[(size_t)RR * CC];
__device__ __align__(16) __nv_bfloat16 g_Kh[(size_t)RR * CC],  g_Kl[(size_t)RR * CC];
__device__ __align__(16) __nv_bfloat16 g_Vh[(size_t)RR * CC],  g_Vl[(size_t)RR * CC];
__device__ __align__(16) __nv_bfloat16 g_L2h[(size_t)RR * CC], g_L2l[(size_t)RR * CC];
__device__ __align__(16) __nv_bfloat16 g_Hh[(size_t)RR * MLPH], g_Hl[(size_t)RR * MLPH];

__device__ __align__(16) __nv_bfloat16 g_wqh[CC * CC],  g_wql[CC * CC];
__device__ __align__(16) __nv_bfloat16 g_wkh[CC * CC],  g_wkl[CC * CC];
__device__ __align__(16) __nv_bfloat16 g_wvh[CC * CC],  g_wvl[CC * CC];
__device__ __align__(16) __nv_bfloat16 g_w1h[MLPH * CC], g_w1l[MLPH * CC]; // w1^T
__device__ __align__(16) __nv_bfloat16 g_w2h[CC * MLPH], g_w2l[CC * MLPH]; // w2^T

// ---------------- helpers ----------------------------------------------------
__device__ __forceinline__ uint32_t smem_u32(const void* p) {
    uint32_t a;
    asm("{ .reg .u64 t; cvta.to.shared.u64 t, %1; cvt.u32.u64 %0, t; }"
        : "=r"(a) : "l"(p));
    return a;
}
__device__ __forceinline__ void cpa16(uint32_t dst, const void* src) {
    asm volatile("cp.async.cg.shared.global [%0], [%1], 16;"
                 :: "r"(dst), "l"(src) : "memory");
}
#define CP_COMMIT() asm volatile("cp.async.commit_group;" ::: "memory")
#define CP_WAIT(n)  asm volatile("cp.async.wait_group %0;" :: "n"(n) : "memory")

__device__ __forceinline__ void ldsm4(uint32_t& r0, uint32_t& r1,
                                      uint32_t& r2, uint32_t& r3, uint32_t a) {
    asm volatile("ldmatrix.sync.aligned.m8n8.x4.shared.b16 {%0,%1,%2,%3}, [%4];"
                 : "=r"(r0), "=r"(r1), "=r"(r2), "=r"(r3) : "r"(a));
}
__device__ __forceinline__ void mma16816(float* c, uint32_t a0, uint32_t a1,
                                         uint32_t a2, uint32_t a3,
                                         uint32_t b0, uint32_t b1) {
    asm volatile(
        "mma.sync.aligned.m16n8k16.row.col.f32.bf16.bf16.f32 "
        "{%0,%1,%2,%3}, {%4,%5,%6,%7}, {%8,%9}, {%0,%1,%2,%3};"
        : "+f"(c[0]), "+f"(c[1]), "+f"(c[2]), "+f"(c[3])
        : "r"(a0), "r"(a1), "r"(a2), "r"(a3), "r"(b0), "r"(b1));
}
__device__ __forceinline__ void bf16_split(float v, __nv_bfloat16& h, __nv_bfloat16& l) {
    h = __float2bfloat16(v);
    l = __float2bfloat16(v - __bfloat162float(h));
}
// smem layout: rows of 32 bf16 (64B); 16B units XOR-swizzled by (row>>1)&3
__device__ __forceinline__ uint32_t swoff(int row, int kb) {
    return (uint32_t)((row << 6) + ((((kb >> 4) ^ ((row >> 1) & 3))) << 4));
}

// ============================================================================
// K1a: per-position LN stats (coalesced along n)
// ============================================================================
__global__ __launch_bounds__(256) void k_stats(
    const float* __restrict__ q,  const float* __restrict__ k,
    const float* __restrict__ qe, const float* __restrict__ ke)
{
    int b  = blockIdx.y;
    int n0 = blockIdx.x * 32;
    int tx = threadIdx.x & 31;
    int ty = threadIdx.x >> 5;     // 0..7
    size_t base = (size_t)b * CC * NN_ + n0 + tx;

    float qs = 0.f, qss = 0.f, ks = 0.f, kss = 0.f;
    for (int c = ty; c < CC; c += 8) {
        size_t idx = base + (size_t)c * NN_;
        float qv = q[idx] + qe[idx];
        float kv = k[idx] + ke[idx];
        qs += qv; qss += qv * qv;
        ks += kv; kss += kv * kv;
    }
    __shared__ float sm[4][8][32];
    sm[0][ty][tx] = qs; sm[1][ty][tx] = qss;
    sm[2][ty][tx] = ks; sm[3][ty][tx] = kss;
    __syncthreads();
    if (ty == 0) {
        float a0 = 0.f, a1 = 0.f, a2 = 0.f, a3 = 0.f;
#pragma unroll
        for (int w = 0; w < 8; w++) {
            a0 += sm[0][w][tx]; a1 += sm[1][w][tx];
            a2 += sm[2][w][tx]; a3 += sm[3][w][tx];
        }
        const float invC = 1.0f / CC;
        float qm = a0 * invC, km = a2 * invC;
        float qrs = rsqrtf(a1 * invC - qm * qm + 1e-5f);
        float krs = rsqrtf(a3 * invC - km * km + 1e-5f);
        g_stats[b * NN_ + n0 + tx] = make_float4(qm, qrs, km, krs);
    }
}

// ============================================================================
// K1b: transpose-convert: apply LN, emit pos-major bf16 hi/lo (+ raw q fp32)
// ============================================================================
__global__ __launch_bounds__(256) void k_cvtT(
    const float* __restrict__ q,  const float* __restrict__ k,
    const float* __restrict__ qe, const float* __restrict__ ke,
    const float* __restrict__ gn, const float* __restrict__ bn)
{
    __shared__ float tQE[32][33], tKE[32][33], tQ[32][33], tK[32][33];
    int b  = blockIdx.z;
    int c0 = blockIdx.y * 32;
    int n0 = blockIdx.x * 32;
    int tx = threadIdx.x;      // 0..31
    int ty = threadIdx.y;      // 0..7

#pragma unroll
    for (int i = 0; i < 4; i++) {
        int cl = ty + i * 8;
        size_t idx = (size_t)b * CC * NN_ + (size_t)(c0 + cl) * NN_ + n0 + tx;
        float qv = q[idx], kv = k[idx];
        tQ [cl][tx] = qv;
        tK [cl][tx] = kv;
        tQE[cl][tx] = qv + qe[idx];
        tKE[cl][tx] = kv + ke[idx];
    }
    __syncthreads();

    int c = c0 + tx;
    float g = gn[c], bb = bn[c];
#pragma unroll
    for (int i = 0; i < 4; i++) {
        int nl = ty + i * 8;
        int r  = b * NN_ + n0 + nl;
        float4 s = g_stats[r];
        float qo = (tQE[tx][nl] - s.x) * s.y * g + bb;
        float ko = (tKE[tx][nl] - s.z) * s.w * g + bb;
        float vr = tK[tx][nl];
        size_t o = (size_t)r * CC + c;
        __nv_bfloat16 h, l;
        bf16_split(qo, h, l); g_Qh[o] = h; g_Ql[o] = l;
        bf16_split(ko, h, l); g_Kh[o] = h; g_Kl[o] = l;
        bf16_split(vr, h, l); g_Vh[o] = h; g_Vl[o] = l;
        g_Qt[o] = tQ[tx][nl];
    }
}

// ============================================================================
// mma.sync split-bf16 GEMM body:  C[M,Nd] = A[M,K] * B[Nd,K]^T (+bias)
// 128x128x32 CTA tile, 8 warps (2x4), double-buffered cp.async, 2 CTAs/SM.
// ============================================================================
#define ST_BYTES 32768          // per stage: Ah 8K | Al 8K | Bh 8K | Bl 8K
#define GEMM_SMEM (2 * ST_BYTES)

__device__ __forceinline__ void ld_tile(uint32_t sdst,
                                        const __nv_bfloat16* __restrict__ src,
                                        int ldk) {
    int tid = threadIdx.x;
#pragma unroll
    for (int it = 0; it < 2; it++) {
        int f   = tid + it * 256;   // 0..511
        int row = f >> 2;           // 0..127
        int u   = f & 3;            // 16B unit within 64B row
        uint32_t d = sdst + (uint32_t)(row << 6) + (uint32_t)(((u ^ ((row >> 1) & 3))) << 4);
        cpa16(d, src + (size_t)row * ldk + u * 8);
    }
}

template <int OUT>
__device__ __forceinline__ void gemm_body(
    const __nv_bfloat16* __restrict__ Ahi, const __nv_bfloat16* __restrict__ Alo,
    const __nv_bfloat16* __restrict__ Bhi, const __nv_bfloat16* __restrict__ Blo,
    const float* __restrict__ bias,
    float* __restrict__ Cf,
    __nv_bfloat16* __restrict__ Chi, __nv_bfloat16* __restrict__ Clo,
    int Nd, int K, int brow, int bcol, char* smem)
{
    uint32_t sb = smem_u32(smem);
    const int tid  = threadIdx.x;
    const int lane = tid & 31;
    const int wid  = tid >> 5;
    const int wr   = wid >> 2;          // 0..1 (64 m rows)
    const int wc   = wid & 3;           // 0..3 (32 n cols)

    float acc[4][4][4];
#pragma unroll
    for (int i = 0; i < 4; i++)
#pragma unroll
        for (int j = 0; j < 4; j++)
#pragma unroll
            for (int x = 0; x < 4; x++) acc[i][j][x] = 0.f;

    const int a_row = wr * 64 + (lane & 15);
    const int a_kb  = (lane & 16);
    const int b_row = wc * 32 + (lane & 7) + ((lane & 16) ? 8 : 0);
    const int b_kb  = ((lane & 8) ? 16 : 0);

    const int NCH = K >> 5;

    {
        ld_tile(sb +     0, Ahi + (size_t)brow * K, K);
        ld_tile(sb +  8192, Alo + (size_t)brow * K, K);
        ld_tile(sb + 16384, Bhi + (size_t)bcol * K, K);
        ld_tile(sb + 24576, Blo + (size_t)bcol * K, K);
        CP_COMMIT();
    }

    for (int ch = 0; ch < NCH; ch++) {
        int s = ch & 1;
        if (ch + 1 < NCH) {
            uint32_t sn = sb + (uint32_t)((s ^ 1) * ST_BYTES);
            int k0 = (ch + 1) << 5;
            ld_tile(sn +     0, Ahi + (size_t)brow * K + k0, K);
            ld_tile(sn +  8192, Alo + (size_t)brow * K + k0, K);
            ld_tile(sn + 16384, Bhi + (size_t)bcol * K + k0, K);
            ld_tile(sn + 24576, Blo + (size_t)bcol * K + k0, K);
            CP_COMMIT();
            CP_WAIT(1);
        } else {
            CP_WAIT(0);
        }
        __syncthreads();

        uint32_t sa = sb + (uint32_t)(s * ST_BYTES);
#pragma unroll
        for (int ks = 0; ks < 2; ks++) {
            int kso = ks * 32;
            uint32_t bh[4][2], bl[4][2];
#pragma unroll
            for (int jp = 0; jp < 2; jp++) {
                uint32_t addr_h = sa + 16384 + swoff(b_row + jp * 16, b_kb + kso);
                uint32_t addr_l = sa + 24576 + swoff(b_row + jp * 16, b_kb + kso);
                ldsm4(bh[2*jp][0], bh[2*jp][1], bh[2*jp+1][0], bh[2*jp+1][1], addr_h);
                ldsm4(bl[2*jp][0], bl[2*jp][1], bl[2*jp+1][0], bl[2*jp+1][1], addr_l);
            }
#pragma unroll
            for (int i = 0; i < 4; i++) {
                uint32_t ah0, ah1, ah2, ah3, al0, al1, al2, al3;
                ldsm4(ah0, ah1, ah2, ah3, sa +    0 + swoff(a_row + i * 16, a_kb + kso));
                ldsm4(al0, al1, al2, al3, sa + 8192 + swoff(a_row + i * 16, a_kb + kso));
#pragma unroll
                for (int j = 0; j < 4; j++) {
                    mma16816(acc[i][j], ah0, ah1, ah2, ah3, bh[j][0], bh[j][1]);
                    mma16816(acc[i][j], ah0, ah1, ah2, ah3, bl[j][0], bl[j][1]);
                    mma16816(acc[i][j], al0, al1, al2, al3, bh[j][0], bh[j][1]);
                }
            }
        }
        __syncthreads();
    }

    const int grp = lane >> 2, qr = lane & 3;
#pragma unroll
    for (int i = 0; i < 4; i++) {
        int r0 = brow + wr * 64 + i * 16 + grp;
#pragma unroll
        for (int j = 0; j < 4; j++) {
            int col = bcol + wc * 32 + j * 8 + qr * 2;
            float b0 = bias[col], b1 = bias[col + 1];
            float v00 = acc[i][j][0] + b0, v01 = acc[i][j][1] + b1;
            float v10 = acc[i][j][2] + b0, v11 = acc[i][j][3] + b1;
            if (OUT == 0) {
                *(float2*)(Cf + (size_t)r0 * Nd + col)       = make_float2(v00, v01);
                *(float2*)(Cf + (size_t)(r0 + 8) * Nd + col) = make_float2(v10, v11);
            } else {
                v00 = 0.5f * v00 * (1.0f + erff(v00 * 0.70710678118654752f));
                v01 = 0.5f * v01 * (1.0f + erff(v01 * 0.70710678118654752f));
                v10 = 0.5f * v10 * (1.0f + erff(v10 * 0.70710678118654752f));
                v11 = 0.5f * v11 * (1.0f + erff(v11 * 0.70710678118654752f));
                __nv_bfloat16 h0, l0, h1, l1;
                bf16_split(v00, h0, l0); bf16_split(v01, h1, l1);
                *(__nv_bfloat162*)(Chi + (size_t)r0 * Nd + col) = __nv_bfloat162(h0, h1);
                *(__nv_bfloat162*)(Clo + (size_t)r0 * Nd + col) = __nv_bfloat162(l0, l1);
                bf16_split(v10, h0, l0); bf16_split(v11, h1, l1);
                *(__nv_bfloat162*)(Chi + (size_t)(r0 + 8) * Nd + col) = __nv_bfloat162(h0, h1);
                *(__nv_bfloat162*)(Clo + (size_t)(r0 + 8) * Nd + col) = __nv_bfloat162(l0, l1);
            }
        }
    }
}

template <int OUT>
__global__ __launch_bounds__(256, 2) void mma_gemm(
    const __nv_bfloat16* __restrict__ Ahi, const __nv_bfloat16* __restrict__ Alo,
    const __nv_bfloat16* __restrict__ Bhi, const __nv_bfloat16* __restrict__ Blo,
    const float* __restrict__ bias,
    float* __restrict__ Cf,
    __nv_bfloat16* __restrict__ Chi, __nv_bfloat16* __restrict__ Clo,
    int Nd, int K)
{
    extern __shared__ char smem[];
    gemm_body<OUT>(Ahi, Alo, Bhi, Blo, bias, Cf, Chi, Clo,
                   Nd, K, blockIdx.y * 128, blockIdx.x * 128, smem);
}

// merged projection GEMM: blockIdx.z selects (Q,K,V)
__global__ __launch_bounds__(256, 2) void mma_gemm_proj(
    const __nv_bfloat16* __restrict__ A0h, const __nv_bfloat16* __restrict__ A0l,
    const __nv_bfloat16* __restrict__ A1h, const __nv_bfloat16* __restrict__ A1l,
    const __nv_bfloat16* __restrict__ A2h, const __nv_bfloat16* __restrict__ A2l,
    const __nv_bfloat16* __restrict__ B0h, const __nv_bfloat16* __restrict__ B0l,
    const __nv_bfloat16* __restrict__ B1h, const __nv_bfloat16* __restrict__ B1l,
    const __nv_bfloat16* __restrict__ B2h, const __nv_bfloat16* __restrict__ B2l,
    const float* __restrict__ b0, const float* __restrict__ b1,
    const float* __restrict__ b2,
    float* __restrict__ C0, float* __restrict__ C1, float* __restrict__ C2)
{
    extern __shared__ char smem[];
    int z = blockIdx.z;
    const __nv_bfloat16* Ah = (z == 0) ? A0h : (z == 1) ? A1h : A2h;
    const __nv_bfloat16* Al = (z == 0) ? A0l : (z == 1) ? A1l : A2l;
    const __nv_bfloat16* Bh = (z == 0) ? B0h : (z == 1) ? B1h : B2h;
    const __nv_bfloat16* Bl = (z == 0) ? B0l : (z == 1) ? B1l : B2l;
    const float* bs = (z == 0) ? b0 : (z == 1) ? b1 : b2;
    float* Cf = (z == 0) ? C0 : (z == 1) ? C1 : C2;
    gemm_body<0>(Ah, Al, Bh, Bl, bs, Cf, nullptr, nullptr,
                 CC, CC, blockIdx.y * 128, blockIdx.x * 128, smem);
}

// ============================================================================
// K4: windowed attention + residual + LN2 (emits bf16 hi/lo for MLP).
// ============================================================================
__global__ __launch_bounds__(256) void k_attn(
    const float* __restrict__ g2, const float* __restrict__ b2)
{
    int r  = blockIdx.x;
    int bb = r >> 11;
    int n  = r & (NN_ - 1);
    int tid = threadIdx.x;
    const float scale = 0.044194173824159216f;  // 512^-0.5

    bool   valid[KH];
    size_t nb[KH];
#pragma unroll
    for (int j = 0; j < KH; j++) {
        int nn = n + j - PAD;
        valid[j] = (nn >= 0) && (nn < NN_);
        nb[j] = valid[j] ? ((size_t)(bb * NN_ + nn)) * CC : 0;
    }

    size_t qb = (size_t)r * CC;
    float acc[KH];
#pragma unroll
    for (int j = 0; j < KH; j++) acc[j] = 0.f;

#pragma unroll
    for (int it = 0; it < 2; it++) {
        int c = tid + it * 256;
        float qv = g_Qp[qb + c];
#pragma unroll
        for (int j = 0; j < KH; j++)
            if (valid[j]) acc[j] = fmaf(qv, g_Kp[nb[j] + c], acc[j]);
    }

    __shared__ float sm[KH][8];
#pragma unroll
    for (int j = 0; j < KH; j++) {
#pragma unroll
        for (int o = 16; o > 0; o >>= 1)
            acc[j] += __shfl_down_sync(0xffffffffu, acc[j], o);
    }
    if ((tid & 31) == 0) {
        int w = tid >> 5;
#pragma unroll
        for (int j = 0; j < KH; j++) sm[j][w] = acc[j];
    }
    __syncthreads();
    __shared__ float wt[KH];
    if (tid < KH) {
        float s = 0.f;
#pragma unroll
        for (int w = 0; w < 8; w++) s += sm[tid][w];
        wt[tid] = s;
    }
    __syncthreads();

    float m = wt[0];
#pragma unroll
    for (int j = 1; j < KH; j++) m = fmaxf(m, wt[j]);
    float wj[KH], es = 0.f;
#pragma unroll
    for (int j = 0; j < KH; j++) { wj[j] = expf(wt[j] - m); es += wj[j]; }
    float inv = scale / es;
#pragma unroll
    for (int j = 0; j < KH; j++) wj[j] *= inv;

    float xv[2], xs = 0.f, xss = 0.f;
#pragma unroll
    for (int it = 0; it < 2; it++) {
        int c = tid + it * 256;
        float s = 0.f;
#pragma unroll
        for (int j = 0; j < KH; j++)
            if (valid[j]) s = fmaf(wj[j], g_Vp[nb[j] + c], s);
        float x = g_Qt[qb + c] + s;
        g_X[qb + c] = x;
        xv[it] = x; xs += x; xss += x * x;
    }
    __syncthreads();
#pragma unroll
    for (int o = 16; o > 0; o >>= 1) {
        xs  += __shfl_down_sync(0xffffffffu, xs,  o);
        xss += __shfl_down_sync(0xffffffffu, xss, o);
    }
    if ((tid & 31) == 0) { int w = tid >> 5; sm[0][w] = xs; sm[1][w] = xss; }
    __syncthreads();
    float fs = 0.f, fss = 0.f;
#pragma unroll
    for (int w = 0; w < 8; w++) { fs += sm[0][w]; fss += sm[1][w]; }
    const float invC = 1.0f / CC;
    float mean = fs * invC;
    float rstd = rsqrtf(fss * invC - mean * mean + 1e-5f);
#pragma unroll
    for (int it = 0; it < 2; it++) {
        int c = tid + it * 256;
        float v = (xv[it] - mean) * rstd * g2[c] + b2[c];
        __nv_bfloat16 h, l;
        bf16_split(v, h, l);
        g_L2h[qb + c] = h; g_L2l[qb + c] = l;
    }
}

// ============================================================================
// weight prep
// ============================================================================
__global__ __launch_bounds__(256) void k_cvt(
    const float* __restrict__ src, __nv_bfloat16* __restrict__ hi,
    __nv_bfloat16* __restrict__ lo, int n)
{
    int i = blockIdx.x * 256 + threadIdx.x;
    if (i < n) {
        __nv_bfloat16 h, l;
        bf16_split(src[i], h, l);
        hi[i] = h; lo[i] = l;
    }
}

// src [R, Cc] fp32 -> dst [Cc, R] bf16 hi/lo
__global__ void k_tcvt(const float* __restrict__ src,
                       __nv_bfloat16* __restrict__ hi,
                       __nv_bfloat16* __restrict__ lo, int R, int Cc)
{
    __shared__ float t[32][33];
    int c0 = blockIdx.x * 32, r0 = blockIdx.y * 32;
    int tx = threadIdx.x, ty = threadIdx.y;
#pragma unroll
    for (int i = 0; i < 4; i++)
        t[ty + i * 8][tx] = src[(size_t)(r0 + ty + i * 8) * Cc + c0 + tx];
    __syncthreads();
#pragma unroll
    for (int i = 0; i < 4; i++) {
        float v = t[tx][ty + i * 8];
        size_t o = (size_t)(c0 + ty + i * 8) * R + r0 + tx;
        __nv_bfloat16 h, l;
        bf16_split(v, h, l);
        hi[o] = h; lo[o] = l;
    }
}

// ============================================================================
// K7: out[b,c,n] = X[r,c] + H2[r,c]
// ============================================================================
__global__ __launch_bounds__(256) void k_out(float* __restrict__ out)
{
    __shared__ float t[32][33];
    int bb = blockIdx.z;
    int c0 = blockIdx.y * 32;
    int n0 = blockIdx.x * 32;
    int tx = threadIdx.x;
    int ty = threadIdx.y;
#pragma unroll
    for (int i = 0; i < 4; i++) {
        int n = n0 + ty + i * 8;
        size_t idx = ((size_t)(bb * NN_ + n)) * CC + c0 + tx;
        t[tx][ty + i * 8] = g_X[idx] + g_H2[idx];
    }
    __syncthreads();
#pragma unroll
    for (int i = 0; i < 4; i++) {
        int c = c0 + ty + i * 8;
        out[(size_t)bb * CC * NN_ + (size_t)c * NN_ + n0 + tx] = t[ty + i * 8][tx];
    }
}

// ============================================================================
extern "C" void kernel_launch(void* const* d_in, const int* in_sizes, int n_in,
                              void* d_out, int out_size)
{
    const float* query = (const float*)d_in[0];
    const float* key   = (const float*)d_in[1];
    const float* qe    = (const float*)d_in[2];
    const float* ke    = (const float*)d_in[3];
    const float* wq    = (const float*)d_in[4];
    const float* bq    = (const float*)d_in[5];
    const float* wk    = (const float*)d_in[6];
    const float* bk    = (const float*)d_in[7];
    const float* wv    = (const float*)d_in[8];
    const float* bv    = (const float*)d_in[9];
    const float* gn    = (const float*)d_in[10];
    const float* bn    = (const float*)d_in[11];
    const float* g2    = (const float*)d_in[12];
    const float* b2    = (const float*)d_in[13];
    const float* w1    = (const float*)d_in[14];
    const float* b1    = (const float*)d_in[15];
    const float* w2    = (const float*)d_in[16];
    const float* b2b   = (const float*)d_in[17];
    float* out = (float*)d_out;

    float *Qp, *Kp, *Vp, *H2;
    __nv_bfloat16 *Qh, *Ql, *Kh, *Kl, *Vh, *Vl, *L2h, *L2l, *Hh, *Hl;
    __nv_bfloat16 *wqh, *wql, *wkh, *wkl, *wvh, *wvl, *w1h, *w1l, *w2h, *w2l;
    cudaGetSymbolAddress((void**)&Qp,  g_Qp);
    cudaGetSymbolAddress((void**)&Kp,  g_Kp);
    cudaGetSymbolAddress((void**)&Vp,  g_Vp);
    cudaGetSymbolAddress((void**)&H2,  g_H2);
    cudaGetSymbolAddress((void**)&Qh,  g_Qh);  cudaGetSymbolAddress((void**)&Ql,  g_Ql);
    cudaGetSymbolAddress((void**)&Kh,  g_Kh);  cudaGetSymbolAddress((void**)&Kl,  g_Kl);
    cudaGetSymbolAddress((void**)&Vh,  g_Vh);  cudaGetSymbolAddress((void**)&Vl,  g_Vl);
    cudaGetSymbolAddress((void**)&L2h, g_L2h); cudaGetSymbolAddress((void**)&L2l, g_L2l);
    cudaGetSymbolAddress((void**)&Hh,  g_Hh);  cudaGetSymbolAddress((void**)&Hl,  g_Hl);
    cudaGetSymbolAddress((void**)&wqh, g_wqh); cudaGetSymbolAddress((void**)&wql, g_wql);
    cudaGetSymbolAddress((void**)&wkh, g_wkh); cudaGetSymbolAddress((void**)&wkl, g_wkl);
    cudaGetSymbolAddress((void**)&wvh, g_wvh); cudaGetSymbolAddress((void**)&wvl, g_wvl);
    cudaGetSymbolAddress((void**)&w1h, g_w1h); cudaGetSymbolAddress((void**)&w1l, g_w1l);
    cudaGetSymbolAddress((void**)&w2h, g_w2h); cudaGetSymbolAddress((void**)&w2l, g_w2l);

    cudaFuncSetAttribute(mma_gemm<0>,  cudaFuncAttributeMaxDynamicSharedMemorySize, GEMM_SMEM);
    cudaFuncSetAttribute(mma_gemm<1>,  cudaFuncAttributeMaxDynamicSharedMemorySize, GEMM_SMEM);
    cudaFuncSetAttribute(mma_gemm_proj, cudaFuncAttributeMaxDynamicSharedMemorySize, GEMM_SMEM);

    // weight prep
    k_cvt<<<(CC * CC + 255) / 256, 256>>>(wq, wqh, wql, CC * CC);
    k_cvt<<<(CC * CC + 255) / 256, 256>>>(wk, wkh, wkl, CC * CC);
    k_cvt<<<(CC * CC + 255) / 256, 256>>>(wv, wvh, wvl, CC * CC);
    k_tcvt<<<dim3(MLPH / 32, CC / 32), dim3(32, 8)>>>(w1, w1h, w1l, CC, MLPH);
    k_tcvt<<<dim3(CC / 32, MLPH / 32), dim3(32, 8)>>>(w2, w2h, w2l, MLPH, CC);

    // 1) LN stats + transpose-convert
    k_stats<<<dim3(NN_ / 32, BB), 256>>>(query, key, qe, ke);
    k_cvtT<<<dim3(NN_ / 32, CC / 32, BB), dim3(32, 8)>>>(query, key, qe, ke, gn, bn);

    // 2) projections (merged NT GEMMs, K=512)
    {
        dim3 g(CC / 128, RR / 128, 3);
        mma_gemm_proj<<<g, 256, GEMM_SMEM>>>(
            Qh, Ql, Kh, Kl, Vh, Vl,
            wqh, wql, wkh, wkl, wvh, wvl,
            bq, bk, bv, Qp, Kp, Vp);
    }

    // 3) attention + residual + LN2
    k_attn<<<RR, 256>>>(g2, b2);

    // 4) MLP1: H = gelu(L2 @ w1^T + b1)   Nd=2048, K=512
    {
        dim3 g(MLPH / 128, RR / 128);
        mma_gemm<1><<<g, 256, GEMM_SMEM>>>(L2h, L2l, w1h, w1l, b1, nullptr, Hh, Hl, MLPH, CC);
    }
    // 5) H2 = H @ w2^T + b2b              Nd=512, K=2048
    {
        dim3 g(CC / 128, RR / 128);
        mma_gemm<0><<<g, 256, GEMM_SMEM>>>(Hh, Hl, w2h, w2l, b2b, H2, nullptr, nullptr, CC, MLPH);
    }

    // 6) out = transpose(X + H2)
    {
        dim3 g(NN_ / 32, CC / 32, BB);
        dim3 blk(32, 8);
        k_out<<<g, blk>>>(out);
    }
}